// round 11
// baseline (speedup 1.0000x reference)
#include <cuda_runtime.h>
#include <cuda_fp16.h>
#include <cstdint>

#define NROWS   262144
#define NSEG    1024
#define HID     256
#define KDIM    256

// ---------------- scratch (device globals: no allocations allowed) ----------
__device__ float  g_scores[NROWS];
__device__ __half g_w1t[HID * KDIM];          // W1^T as fp16, [n][k]
__device__ __half g_xh[(size_t)NROWS * KDIM]; // fp16 copy of x (written by k_scores)
__device__ int    g_segstart[NSEG + 1];

// ---------------- helpers ----------------------------------------------------
static __device__ __forceinline__ uint32_t smem_u32(const void* p) {
    uint32_t a;
    asm("{ .reg .u64 t; cvta.to.shared.u64 t, %1; cvt.u32.u64 %0, t; }"
        : "=r"(a) : "l"(p));
    return a;
}

static __device__ __forceinline__ void ldsm_x4(uint32_t a, uint32_t& r0, uint32_t& r1,
                                               uint32_t& r2, uint32_t& r3) {
    asm volatile("ldmatrix.sync.aligned.m8n8.x4.shared.b16 {%0,%1,%2,%3}, [%4];"
                 : "=r"(r0), "=r"(r1), "=r"(r2), "=r"(r3) : "r"(a));
}

static __device__ __forceinline__ void mma_f16(float* c,
                                               uint32_t a0, uint32_t a1, uint32_t a2, uint32_t a3,
                                               uint32_t b0, uint32_t b1) {
    asm volatile("mma.sync.aligned.m16n8k16.row.col.f32.f16.f16.f32 "
                 "{%0,%1,%2,%3}, {%4,%5,%6,%7}, {%8,%9}, {%0,%1,%2,%3};"
                 : "+f"(c[0]), "+f"(c[1]), "+f"(c[2]), "+f"(c[3])
                 : "r"(a0), "r"(a1), "r"(a2), "r"(a3), "r"(b0), "r"(b1));
}

static __device__ __forceinline__ uint32_t pack_h2(float a, float b) {
    __half2 h = __floats2half2_rn(a, b);
    return *(uint32_t*)&h;
}

static __device__ __forceinline__ void bar_named(int id, int cnt) {
    asm volatile("bar.sync %0, %1;" :: "r"(id), "r"(cnt) : "memory");
}

// ---------------- kernel 1: W1^T -> fp16  +  boundary scan -------------------
__global__ void k_prep(const float* __restrict__ W1,
                       const void* __restrict__ batch_raw) {
    if (blockIdx.x < 256) {
        int k = blockIdx.x, n = threadIdx.x;
        g_w1t[n * KDIM + k] = __float2half_rn(W1[k * HID + n]);
        return;
    }
    const int* b32 = (const int*)batch_raw;
    const long long* b64 = (const long long*)batch_raw;
    bool is64 = (b32[NROWS - 1] == 0) && (b32[NROWS - 3] == 0) &&
                (b32[NROWS - 5] == 0) && (b32[NROWS - 7] == 0);
    int tid = (blockIdx.x - 256) * 256 + threadIdx.x;   // 0..65535
    #pragma unroll
    for (int q = 0; q < 4; q++) {
        int i = tid * 4 + q;
        if (i >= NROWS) break;
        int v = is64 ? (int)b64[i] : b32[i];
        if (i == 0) {
            for (int g = 0; g <= v; g++) g_segstart[g] = 0;
        }
        if (i == NROWS - 1) {
            for (int g = v + 1; g <= NSEG; g++) g_segstart[g] = NROWS;
        } else {
            int v1 = is64 ? (int)b64[i + 1] : b32[i + 1];
            for (int g = v + 1; g <= v1; g++) g_segstart[g] = i + 1;
        }
    }
}

// ---------------- kernel 3: scores, block-barrier-free staging ---------------
// Per CTA: M=128, N=256 in 4 chunks of 64, K=256. 2 CTAs/SM.
// A band mw staged/consumed by warp pair {mw, mw+4} (named barrier 1+mw, 64 thr).
// B half nw staged/consumed by warp quad {4nw..4nw+3} (named barrier 5+nw, 128 thr).
#define SM_A   0          // 128 x 256 fp16, swizzled           (65536)
#define SM_B   65536      // 64 x 256 fp16 chunk of W1^T        (32768)
#define SM_SC  98304      // 128 f32 partial scores             (512)
#define SM_B1  98816      // 256 f32                            (1024)
#define SM_W2  99840      // 256 f32                            (1024)
#define SMEM_SCORES_TOTAL 100864

__global__ void __launch_bounds__(256, 2)
k_scores(const float* __restrict__ x, const float* __restrict__ b1,
         const float* __restrict__ W2, const float* __restrict__ b2) {
    extern __shared__ char smem[];
    uint32_t sb = smem_u32(smem);
    int tid = threadIdx.x, wid = tid >> 5, lid = tid & 31;
    size_t rowbase = (size_t)blockIdx.x * 128;
    int mw = wid & 3, nw = wid >> 2;              // warp grid: 4 (M) x 2 (N)
    int q = tid & 127;                            // index within nw-quad
    int p = lid + ((wid >> 2) << 5);              // index within mw-pair (0..63)

    const uint4* wp = (const uint4*)g_w1t;        // row stride = 32 uint4

    // preload B chunk 0 (own quad half: local rows nw*32..nw*32+31)
    uint4 breg[8];
    #pragma unroll
    for (int i = 0; i < 8; i++) {
        int idx = q + i * 128;                    // 0..1023
        int nl = idx >> 5, c = idx & 31;
        breg[i] = wp[(nw * 32 + nl) * 32 + c];
    }

    // quad-scoped constants: cols with ((col>>5)&1)==nw
    {
        int col = ((q >> 5) << 6) + nw * 32 + (q & 31);
        ((float*)(smem + SM_B1))[col] = b1[col];
        ((float*)(smem + SM_W2))[col] = W2[col];
    }
    // pair-scoped score accumulator init
    if (nw == 0) ((float*)(smem + SM_SC))[mw * 32 + lid] = 0.f;

    // ---- stage own A band: rows mw*32..mw*32+31, f32 -> fp16 + g_xh ----
    {
        const float4* xp = (const float4*)(x + rowbase * 256);
        uint4* xh_out = (uint4*)(g_xh + rowbase * 256);
        #pragma unroll
        for (int i = 0; i < 16; i++) {
            int idx = p + i * 64;                 // 0..1023
            int rl = idx >> 5, c = idx & 31;
            int r = mw * 32 + rl;
            float4 v0 = __ldg(&xp[r * 64 + c * 2]);
            float4 v1 = __ldg(&xp[r * 64 + c * 2 + 1]);
            uint4 hv;
            hv.x = pack_h2(v0.x, v0.y);
            hv.y = pack_h2(v0.z, v0.w);
            hv.z = pack_h2(v1.x, v1.y);
            hv.w = pack_h2(v1.z, v1.w);
            *(uint4*)(smem + SM_A + r * 512 + ((c ^ (r & 7)) << 4)) = hv;
            xh_out[r * 32 + c] = hv;
        }
    }
    bar_named(1 + mw, 64);                        // own A band ready

    // ---- per-lane fragment address invariants ----
    int g = lid >> 2, t = lid & 3, r8 = lid & 7, j = lid >> 3;
    int arow = mw * 32 + (j & 1) * 8 + r8;
    uint32_t aoff0 = SM_A + arow * 512;
    int arm = arow & 7, ac0 = j >> 1;
    int nloc = nw * 32 + (j >> 1) * 8 + r8;
    uint32_t boff0 = SM_B + nloc * 512;
    int bnm = nloc & 7, bc0 = j & 1;

    const float* smB1 = (const float*)(smem + SM_B1);
    const float* smW2 = (const float*)(smem + SM_W2);
    float part[4] = {0.f, 0.f, 0.f, 0.f};         // rows mw*32 + {g, g+8, 16+g, 24+g}

    for (int ch = 0; ch < 4; ch++) {
        if (ch > 0) bar_named(5 + nw, 128);       // quad's prev MMA reads done
        // commit own quad half of B chunk (local rows nw*32..+31)
        #pragma unroll
        for (int i = 0; i < 8; i++) {
            int idx = q + i * 128;
            int nl = idx >> 5, c = idx & 31;
            int nr = nw * 32 + nl;
            *(uint4*)(smem + SM_B + nr * 512 + ((c ^ (nr & 7)) << 4)) = breg[i];
        }
        if (ch < 3) {                             // prefetch next chunk's half
            #pragma unroll
            for (int i = 0; i < 8; i++) {
                int idx = q + i * 128;
                int nl = idx >> 5, c = idx & 31;
                breg[i] = wp[((ch + 1) * 64 + nw * 32 + nl) * 32 + c];
            }
        }
        bar_named(5 + nw, 128);                   // quad's B half visible

        float acc[2][4][4];
        #pragma unroll
        for (int a = 0; a < 2; a++)
            #pragma unroll
            for (int b = 0; b < 4; b++)
                #pragma unroll
                for (int cc = 0; cc < 4; cc++) acc[a][b][cc] = 0.f;

        #pragma unroll 8
        for (int ks = 0; ks < 16; ks++) {
            uint32_t sa = (uint32_t)(((2 * ks + ac0) ^ arm) << 4);
            uint32_t so = (uint32_t)(((2 * ks + bc0) ^ bnm) << 4);
            uint32_t a0[4], a1[4], b0[4], b1r[4];
            ldsm_x4(sb + aoff0 + sa,        a0[0], a0[1], a0[2], a0[3]);
            ldsm_x4(sb + aoff0 + 8192 + sa, a1[0], a1[1], a1[2], a1[3]);
            ldsm_x4(sb + boff0 + so,        b0[0], b0[1], b0[2], b0[3]);
            ldsm_x4(sb + boff0 + 8192 + so, b1r[0], b1r[1], b1r[2], b1r[3]);

            mma_f16(acc[0][0], a0[0], a0[1], a0[2], a0[3], b0[0],  b0[1]);
            mma_f16(acc[0][1], a0[0], a0[1], a0[2], a0[3], b0[2],  b0[3]);
            mma_f16(acc[0][2], a0[0], a0[1], a0[2], a0[3], b1r[0], b1r[1]);
            mma_f16(acc[0][3], a0[0], a0[1], a0[2], a0[3], b1r[2], b1r[3]);
            mma_f16(acc[1][0], a1[0], a1[1], a1[2], a1[3], b0[0],  b0[1]);
            mma_f16(acc[1][1], a1[0], a1[1], a1[2], a1[3], b0[2],  b0[3]);
            mma_f16(acc[1][2], a1[0], a1[1], a1[2], a1[3], b1r[0], b1r[1]);
            mma_f16(acc[1][3], a1[0], a1[1], a1[2], a1[3], b1r[2], b1r[3]);
        }

        // chunk epilogue: fold h -> relu(h + b1) . W2 into per-row partials
        int colb = ch * 64 + nw * 32 + 2 * t;
        #pragma unroll
        for (int nt = 0; nt < 4; nt++) {
            float bv0 = smB1[colb + nt * 8],     bv1 = smB1[colb + nt * 8 + 1];
            float wv0 = smW2[colb + nt * 8],     wv1 = smW2[colb + nt * 8 + 1];
            #pragma unroll
            for (int mt = 0; mt < 2; mt++) {
                part[mt * 2 + 0] += fmaxf(acc[mt][nt][0] + bv0, 0.f) * wv0
                                  + fmaxf(acc[mt][nt][1] + bv1, 0.f) * wv1;
                part[mt * 2 + 1] += fmaxf(acc[mt][nt][2] + bv0, 0.f) * wv0
                                  + fmaxf(acc[mt][nt][3] + bv1, 0.f) * wv1;
            }
        }
    }

    // reduce over the 4 lanes (t) that share each row
    #pragma unroll
    for (int pp = 0; pp < 4; pp++) {
        part[pp] += __shfl_xor_sync(0xffffffffu, part[pp], 1);
        part[pp] += __shfl_xor_sync(0xffffffffu, part[pp], 2);
    }
    if (t == 0) {
        float* sc = (float*)(smem + SM_SC);
        atomicAdd(&sc[mw * 32 + g],      part[0]);
        atomicAdd(&sc[mw * 32 + 8 + g],  part[1]);
        atomicAdd(&sc[mw * 32 + 16 + g], part[2]);
        atomicAdd(&sc[mw * 32 + 24 + g], part[3]);
    }
    bar_named(1 + mw, 64);                        // both pair warps' atomics done
    if (nw == 0)
        g_scores[rowbase + mw * 32 + lid] =
            ((float*)(smem + SM_SC))[mw * 32 + lid] + __ldg(b2);
}

// ---------------- kernel 4: segment softmax + weighted pooling (fp16 x) -----
__global__ void __launch_bounds__(256)
k_pool(float* __restrict__ out) {
    __shared__ float wbuf[1024];
    __shared__ float red[256];
    __shared__ float red2x[128];
    __shared__ float red2y[128];
    int g = blockIdx.x, t = threadIdx.x;
    int rp = t >> 7, cp = t & 127;
    int s0 = g_segstart[g], s1 = g_segstart[g + 1];

    float m = 0.f;
    for (int i = s0 + t; i < s1; i += 256) m = fmaxf(m, g_scores[i]);
    red[t] = m; __syncthreads();
    #pragma unroll
    for (int st = 128; st > 0; st >>= 1) {
        if (t < st) red[t] = fmaxf(red[t], red[t + st]);
        __syncthreads();
    }
    m = red[0]; __syncthreads();

    float den = 0.f;
    float ax[4] = {0.f, 0.f, 0.f, 0.f};
    float ay[4] = {0.f, 0.f, 0.f, 0.f};
    const __half2* xh2 = (const __half2*)g_xh;
    for (int base = s0; base < s1; base += 1024) {
        int n = min(1024, s1 - base);
        for (int i = t; i < n; i += 256) {
            float e = __expf(g_scores[base + i] - m);
            wbuf[i] = e;
            den += e;
        }
        __syncthreads();
        const __half2* xb = xh2 + (size_t)base * 128 + cp;
        int i = rp;
        for (; i + 6 < n; i += 8) {
            float2 v0 = __half22float2(xb[(size_t)(i + 0) * 128]);
            float2 v1 = __half22float2(xb[(size_t)(i + 2) * 128]);
            float2 v2 = __half22float2(xb[(size_t)(i + 4) * 128]);
            float2 v3 = __half22float2(xb[(size_t)(i + 6) * 128]);
            float w0 = wbuf[i], w1 = wbuf[i + 2], w2 = wbuf[i + 4], w3 = wbuf[i + 6];
            ax[0] = fmaf(v0.x, w0, ax[0]); ay[0] = fmaf(v0.y, w0, ay[0]);
            ax[1] = fmaf(v1.x, w1, ax[1]); ay[1] = fmaf(v1.y, w1, ay[1]);
            ax[2] = fmaf(v2.x, w2, ax[2]); ay[2] = fmaf(v2.y, w2, ay[2]);
            ax[3] = fmaf(v3.x, w3, ax[3]); ay[3] = fmaf(v3.y, w3, ay[3]);
        }
        for (; i < n; i += 2) {
            float2 v = __half22float2(xb[(size_t)i * 128]);
            float w = wbuf[i];
            ax[0] = fmaf(v.x, w, ax[0]); ay[0] = fmaf(v.y, w, ay[0]);
        }
        __syncthreads();
    }
    float axs = (ax[0] + ax[1]) + (ax[2] + ax[3]);
    float ays = (ay[0] + ay[1]) + (ay[2] + ay[3]);

    red[t] = den; __syncthreads();
    #pragma unroll
    for (int st = 128; st > 0; st >>= 1) {
        if (t < st) red[t] += red[t + st];
        __syncthreads();
    }
    den = red[0] + 1e-9f;
    __syncthreads();

    if (rp == 1) { red2x[cp] = axs; red2y[cp] = ays; }
    __syncthreads();
    if (rp == 0) {
        out[g * 256 + 2 * cp]     = (axs + red2x[cp]) / den;
        out[g * 256 + 2 * cp + 1] = (ays + red2y[cp]) / den;
    }
}

// ---------------- launch ----------------------------------------------------
extern "C" void kernel_launch(void* const* d_in, const int* in_sizes, int n_in,
                              void* d_out, int out_size) {
    const float* x = 0; const float* W1 = 0; const float* b1 = 0;
    const float* W2 = 0; const float* b2 = 0; const void* batch = 0;
    for (int i = 0; i < n_in; i++) {
        switch (in_sizes[i]) {
            case 67108864: x = (const float*)d_in[i]; break;
            case 65536:    W1 = (const float*)d_in[i]; break;
            case 262144:   batch = d_in[i]; break;
            case 1:        b2 = (const float*)d_in[i]; break;
            case 256:
                if (!b1) b1 = (const float*)d_in[i];
                else     W2 = (const float*)d_in[i];
                break;
            default: break;
        }
    }
    if (!x)     x     = (const float*)d_in[0];
    if (!W1)    W1    = (const float*)d_in[1];
    if (!b1)    b1    = (const float*)d_in[2];
    if (!W2)    W2    = (const float*)d_in[3];
    if (!b2)    b2    = (const float*)d_in[4];
    if (!batch) batch = d_in[5];

    cudaFuncSetAttribute(k_scores, cudaFuncAttributeMaxDynamicSharedMemorySize,
                         SMEM_SCORES_TOTAL);

    k_prep<<<512, 256>>>(W1, batch);
    k_scores<<<NROWS / 128, 256, SMEM_SCORES_TOTAL>>>(x, b1, W2, b2);
    k_pool<<<NSEG, 256>>>((float*)d_out);
}

// round 12
// speedup vs baseline: 1.3637x; 1.3637x over previous
#include <cuda_runtime.h>
#include <cuda_fp16.h>
#include <cstdint>

#define NROWS   262144
#define NSEG    1024
#define HID     256
#define KDIM    256

// ---------------- scratch (device globals: no allocations allowed) ----------
__device__ float  g_scores[NROWS];
__device__ __half g_w1t[HID * KDIM];          // W1^T as fp16, [n][k]
__device__ __half g_xh[(size_t)NROWS * KDIM]; // fp16 copy of x (written by k_scores)
__device__ int    g_segstart[NSEG + 1];

// ---------------- helpers ----------------------------------------------------
static __device__ __forceinline__ uint32_t smem_u32(const void* p) {
    uint32_t a;
    asm("{ .reg .u64 t; cvta.to.shared.u64 t, %1; cvt.u32.u64 %0, t; }"
        : "=r"(a) : "l"(p));
    return a;
}

static __device__ __forceinline__ void ldsm_x4(uint32_t a, uint32_t& r0, uint32_t& r1,
                                               uint32_t& r2, uint32_t& r3) {
    asm volatile("ldmatrix.sync.aligned.m8n8.x4.shared.b16 {%0,%1,%2,%3}, [%4];"
                 : "=r"(r0), "=r"(r1), "=r"(r2), "=r"(r3) : "r"(a));
}

static __device__ __forceinline__ void mma_f16(float* c,
                                               uint32_t a0, uint32_t a1, uint32_t a2, uint32_t a3,
                                               uint32_t b0, uint32_t b1) {
    asm volatile("mma.sync.aligned.m16n8k16.row.col.f32.f16.f16.f32 "
                 "{%0,%1,%2,%3}, {%4,%5,%6,%7}, {%8,%9}, {%0,%1,%2,%3};"
                 : "+f"(c[0]), "+f"(c[1]), "+f"(c[2]), "+f"(c[3])
                 : "r"(a0), "r"(a1), "r"(a2), "r"(a3), "r"(b0), "r"(b1));
}

static __device__ __forceinline__ uint32_t pack_h2(float a, float b) {
    __half2 h = __floats2half2_rn(a, b);
    return *(uint32_t*)&h;
}

// ---------------- kernel 1: W1^T -> fp16  +  boundary scan -------------------
__global__ void k_prep(const float* __restrict__ W1,
                       const void* __restrict__ batch_raw) {
    if (blockIdx.x < 256) {
        int k = blockIdx.x, n = threadIdx.x;
        g_w1t[n * KDIM + k] = __float2half_rn(W1[k * HID + n]);
        return;
    }
    const int* b32 = (const int*)batch_raw;
    const long long* b64 = (const long long*)batch_raw;
    bool is64 = (b32[NROWS - 1] == 0) && (b32[NROWS - 3] == 0) &&
                (b32[NROWS - 5] == 0) && (b32[NROWS - 7] == 0);
    int tid = (blockIdx.x - 256) * 256 + threadIdx.x;   // 0..65535
    #pragma unroll
    for (int q = 0; q < 4; q++) {
        int i = tid * 4 + q;
        if (i >= NROWS) break;
        int v = is64 ? (int)b64[i] : b32[i];
        if (i == 0) {
            for (int g = 0; g <= v; g++) g_segstart[g] = 0;
        }
        if (i == NROWS - 1) {
            for (int g = v + 1; g <= NSEG; g++) g_segstart[g] = NROWS;
        } else {
            int v1 = is64 ? (int)b64[i + 1] : b32[i + 1];
            for (int g = v + 1; g <= v1; g++) g_segstart[g] = i + 1;
        }
    }
}

// ---------------- kernel 3: scores via mma.sync fp16 (R5/R10 structure) ------
// Per CTA: M=128 rows, N=256 in 4 chunks of 64, K=256. 2 CTAs/SM.
#define SM_A   0          // 128 x 256 fp16, swizzled           (65536)
#define SM_B   65536      // 64 x 256 fp16 chunk of W1^T        (32768)
#define SM_SC  98304      // 128 f32 partial scores             (512)
#define SM_B1  98816      // 256 f32                            (1024)
#define SM_W2  99840      // 256 f32                            (1024)
#define SMEM_SCORES_TOTAL 100864

__global__ void __launch_bounds__(256, 2)
k_scores(const float* __restrict__ x, const float* __restrict__ b1,
         const float* __restrict__ W2, const float* __restrict__ b2) {
    extern __shared__ char smem[];
    uint32_t sb = smem_u32(smem);
    int tid = threadIdx.x, wid = tid >> 5, lid = tid & 31;
    size_t rowbase = (size_t)blockIdx.x * 128;
    int mw = wid & 3, nw = wid >> 2;              // warp grid: 4 (M) x 2 (N)

    // preload B chunk 0 into registers (hides L2 latency behind A staging)
    const uint4* wp = (const uint4*)g_w1t;        // 2048 uint4 per 64-row chunk
    uint4 breg[8];
    #pragma unroll
    for (int i = 0; i < 8; i++) breg[i] = wp[tid + i * 256];

    // stage constants, zero score accumulator
    if (tid < 128) ((float*)(smem + SM_SC))[tid] = 0.f;
    ((float*)(smem + SM_B1))[tid] = b1[tid];
    ((float*)(smem + SM_W2))[tid] = W2[tid];

    // ---- stage A tile: 128x256 f32 -> fp16, swizzled; also write g_xh ----
    {
        const float4* xp = (const float4*)(x + rowbase * 256);
        uint4* xh_out = (uint4*)(g_xh + rowbase * 256);
        #pragma unroll
        for (int i = 0; i < 16; i++) {
            int cid = tid + i * 256;              // 0..4095 chunks of 8 elems
            int row = cid >> 5, c = cid & 31;
            float4 v0 = __ldg(&xp[row * 64 + c * 2]);
            float4 v1 = __ldg(&xp[row * 64 + c * 2 + 1]);
            uint4 hv;
            hv.x = pack_h2(v0.x, v0.y);
            hv.y = pack_h2(v0.z, v0.w);
            hv.z = pack_h2(v1.x, v1.y);
            hv.w = pack_h2(v1.z, v1.w);
            uint32_t off = row * 512 + ((c ^ (row & 7)) << 4);
            *(uint4*)(smem + SM_A + off) = hv;
            xh_out[row * 32 + c] = hv;            // coalesced fp16 copy of x
        }
    }

    // ---- per-lane fragment address invariants ----
    int g = lid >> 2, t = lid & 3, r8 = lid & 7, j = lid >> 3;
    int arow = mw * 32 + (j & 1) * 8 + r8;
    uint32_t aoff0 = SM_A + arow * 512;
    int arm = arow & 7, ac0 = j >> 1;
    int nloc = nw * 32 + (j >> 1) * 8 + r8;
    uint32_t boff0 = SM_B + nloc * 512;
    int bnm = nloc & 7, bc0 = j & 1;

    const float* smB1 = (const float*)(smem + SM_B1);
    const float* smW2 = (const float*)(smem + SM_W2);
    float part[4] = {0.f, 0.f, 0.f, 0.f};         // rows mw*32 + {g, g+8, 16+g, 24+g}

    for (int ch = 0; ch < 4; ch++) {
        __syncthreads();                          // prev B reads done / A staged
        // commit preloaded B chunk to smem (swizzled)
        #pragma unroll
        for (int i = 0; i < 8; i++) {
            int cid = tid + i * 256;              // == nl*32 + c
            int nl = cid >> 5, c = cid & 31;
            *(uint4*)(smem + SM_B + nl * 512 + ((c ^ (nl & 7)) << 4)) = breg[i];
        }
        // issue next chunk's loads now; latency hides under the MMA loop
        if (ch < 3) {
            #pragma unroll
            for (int i = 0; i < 8; i++)
                breg[i] = wp[(ch + 1) * 2048 + tid + i * 256];
        }
        __syncthreads();

        float acc[2][4][4];
        #pragma unroll
        for (int a = 0; a < 2; a++)
            #pragma unroll
            for (int b = 0; b < 4; b++)
                #pragma unroll
                for (int cc = 0; cc < 4; cc++) acc[a][b][cc] = 0.f;

        #pragma unroll 8
        for (int ks = 0; ks < 16; ks++) {
            uint32_t sa = (uint32_t)(((2 * ks + ac0) ^ arm) << 4);
            uint32_t so = (uint32_t)(((2 * ks + bc0) ^ bnm) << 4);
            uint32_t a0[4], a1[4], b0[4], b1r[4];
            ldsm_x4(sb + aoff0 + sa,        a0[0], a0[1], a0[2], a0[3]);
            ldsm_x4(sb + aoff0 + 8192 + sa, a1[0], a1[1], a1[2], a1[3]);
            ldsm_x4(sb + boff0 + so,        b0[0], b0[1], b0[2], b0[3]);
            ldsm_x4(sb + boff0 + 8192 + so, b1r[0], b1r[1], b1r[2], b1r[3]);

            mma_f16(acc[0][0], a0[0], a0[1], a0[2], a0[3], b0[0],  b0[1]);
            mma_f16(acc[0][1], a0[0], a0[1], a0[2], a0[3], b0[2],  b0[3]);
            mma_f16(acc[0][2], a0[0], a0[1], a0[2], a0[3], b1r[0], b1r[1]);
            mma_f16(acc[0][3], a0[0], a0[1], a0[2], a0[3], b1r[2], b1r[3]);
            mma_f16(acc[1][0], a1[0], a1[1], a1[2], a1[3], b0[0],  b0[1]);
            mma_f16(acc[1][1], a1[0], a1[1], a1[2], a1[3], b0[2],  b0[3]);
            mma_f16(acc[1][2], a1[0], a1[1], a1[2], a1[3], b1r[0], b1r[1]);
            mma_f16(acc[1][3], a1[0], a1[1], a1[2], a1[3], b1r[2], b1r[3]);
        }

        // chunk epilogue: fold h -> relu(h + b1) . W2 into per-row partials
        int colb = ch * 64 + nw * 32 + 2 * t;
        #pragma unroll
        for (int nt = 0; nt < 4; nt++) {
            float bv0 = smB1[colb + nt * 8],     bv1 = smB1[colb + nt * 8 + 1];
            float wv0 = smW2[colb + nt * 8],     wv1 = smW2[colb + nt * 8 + 1];
            #pragma unroll
            for (int mt = 0; mt < 2; mt++) {
                part[mt * 2 + 0] += fmaxf(acc[mt][nt][0] + bv0, 0.f) * wv0
                                  + fmaxf(acc[mt][nt][1] + bv1, 0.f) * wv1;
                part[mt * 2 + 1] += fmaxf(acc[mt][nt][2] + bv0, 0.f) * wv0
                                  + fmaxf(acc[mt][nt][3] + bv1, 0.f) * wv1;
            }
        }
    }

    // reduce over the 4 lanes (t) that share each row
    #pragma unroll
    for (int p = 0; p < 4; p++) {
        part[p] += __shfl_xor_sync(0xffffffffu, part[p], 1);
        part[p] += __shfl_xor_sync(0xffffffffu, part[p], 2);
    }
    if (t == 0) {
        float* sc = (float*)(smem + SM_SC);
        atomicAdd(&sc[mw * 32 + g],      part[0]);
        atomicAdd(&sc[mw * 32 + 8 + g],  part[1]);
        atomicAdd(&sc[mw * 32 + 16 + g], part[2]);
        atomicAdd(&sc[mw * 32 + 24 + g], part[3]);
    }
    __syncthreads();
    if (tid < 128)
        g_scores[rowbase + tid] = ((float*)(smem + SM_SC))[tid] + __ldg(b2);
}

// ---------------- kernel 4: segment softmax + weighted pooling (fp16 x) -----
// 256 threads = 8 row-groups x 32 column-lanes; each lane loads uint4 (8 cols).
__global__ void __launch_bounds__(256)
k_pool(float* __restrict__ out) {
    __shared__ float wbuf[1024];
    __shared__ float red[256];
    __shared__ float accs[8][256];      // [row group][col]
    int g = blockIdx.x, t = threadIdx.x;
    int rg = t >> 5;                    // row group 0..7
    int cl = t & 31;                    // column lane: cols cl*8 .. cl*8+7
    int s0 = g_segstart[g], s1 = g_segstart[g + 1];

    // segment max, clamped at >= 0 (scatter-amax-into-zeros semantics)
    float m = 0.f;
    for (int i = s0 + t; i < s1; i += 256) m = fmaxf(m, g_scores[i]);
    red[t] = m; __syncthreads();
    #pragma unroll
    for (int st = 128; st > 0; st >>= 1) {
        if (t < st) red[t] = fmaxf(red[t], red[t + st]);
        __syncthreads();
    }
    m = red[0]; __syncthreads();

    float den = 0.f;
    float ac[8] = {0.f, 0.f, 0.f, 0.f, 0.f, 0.f, 0.f, 0.f};
    const uint4* xh4 = (const uint4*)g_xh;          // 32 uint4 per row
    for (int base = s0; base < s1; base += 1024) {
        int n = min(1024, s1 - base);
        for (int i = t; i < n; i += 256) {
            float e = __expf(g_scores[base + i] - m);
            wbuf[i] = e;
            den += e;
        }
        __syncthreads();
        const uint4* xb = xh4 + (size_t)base * 32 + cl;
        int i = rg;
        for (; i + 24 < n; i += 32) {               // rows i, i+8, i+16, i+24
            uint4 v0 = xb[(size_t)(i +  0) * 32];
            uint4 v1 = xb[(size_t)(i +  8) * 32];
            uint4 v2 = xb[(size_t)(i + 16) * 32];
            uint4 v3 = xb[(size_t)(i + 24) * 32];
            float w0 = wbuf[i], w1 = wbuf[i + 8], w2 = wbuf[i + 16], w3 = wbuf[i + 24];
            #pragma unroll
            for (int h = 0; h < 4; h++) {
                float2 p0 = __half22float2(*(((const __half2*)&v0) + h));
                float2 p1 = __half22float2(*(((const __half2*)&v1) + h));
                float2 p2 = __half22float2(*(((const __half2*)&v2) + h));
                float2 p3 = __half22float2(*(((const __half2*)&v3) + h));
                ac[2*h]   = fmaf(p0.x, w0, ac[2*h]);
                ac[2*h+1] = fmaf(p0.y, w0, ac[2*h+1]);
                ac[2*h]   = fmaf(p1.x, w1, ac[2*h]);
                ac[2*h+1] = fmaf(p1.y, w1, ac[2*h+1]);
                ac[2*h]   = fmaf(p2.x, w2, ac[2*h]);
                ac[2*h+1] = fmaf(p2.y, w2, ac[2*h+1]);
                ac[2*h]   = fmaf(p3.x, w3, ac[2*h]);
                ac[2*h+1] = fmaf(p3.y, w3, ac[2*h+1]);
            }
        }
        for (; i < n; i += 8) {
            uint4 v = xb[(size_t)i * 32];
            float w = wbuf[i];
            #pragma unroll
            for (int h = 0; h < 4; h++) {
                float2 p = __half22float2(*(((const __half2*)&v) + h));
                ac[2*h]   = fmaf(p.x, w, ac[2*h]);
                ac[2*h+1] = fmaf(p.y, w, ac[2*h+1]);
            }
        }
        __syncthreads();
    }

    // reduce denominator
    red[t] = den; __syncthreads();
    #pragma unroll
    for (int st = 128; st > 0; st >>= 1) {
        if (t < st) red[t] += red[t + st];
        __syncthreads();
    }
    den = red[0] + 1e-9f;
    __syncthreads();

    // combine row-group partials: accs[rg][col]
    #pragma unroll
    for (int h = 0; h < 8; h++) accs[rg][cl * 8 + h] = ac[h];
    __syncthreads();
    float s = 0.f;
    #pragma unroll
    for (int r = 0; r < 8; r++) s += accs[r][t];
    out[g * 256 + t] = s / den;
}

// ---------------- launch ----------------------------------------------------
extern "C" void kernel_launch(void* const* d_in, const int* in_sizes, int n_in,
                              void* d_out, int out_size) {
    const float* x = 0; const float* W1 = 0; const float* b1 = 0;
    const float* W2 = 0; const float* b2 = 0; const void* batch = 0;
    for (int i = 0; i < n_in; i++) {
        switch (in_sizes[i]) {
            case 67108864: x = (const float*)d_in[i]; break;
            case 65536:    W1 = (const float*)d_in[i]; break;
            case 262144:   batch = d_in[i]; break;
            case 1:        b2 = (const float*)d_in[i]; break;
            case 256:
                if (!b1) b1 = (const float*)d_in[i];
                else     W2 = (const float*)d_in[i];
                break;
            default: break;
        }
    }
    if (!x)     x     = (const float*)d_in[0];
    if (!W1)    W1    = (const float*)d_in[1];
    if (!b1)    b1    = (const float*)d_in[2];
    if (!W2)    W2    = (const float*)d_in[3];
    if (!b2)    b2    = (const float*)d_in[4];
    if (!batch) batch = d_in[5];

    cudaFuncSetAttribute(k_scores, cudaFuncAttributeMaxDynamicSharedMemorySize,
                         SMEM_SCORES_TOTAL);

    k_prep<<<512, 256>>>(W1, batch);
    k_scores<<<NROWS / 128, 256, SMEM_SCORES_TOTAL>>>(x, b1, W2, b2);
    k_pool<<<NSEG, 256>>>((float*)d_out);
}

// round 13
// speedup vs baseline: 1.6146x; 1.1840x over previous
#include <cuda_runtime.h>
#include <cuda_fp16.h>
#include <cstdint>

#define NROWS   262144
#define NSEG    1024
#define HID     256
#define KDIM    256

// ---------------- scratch (device globals: no allocations allowed) ----------
__device__ float  g_scores[NROWS];
__device__ __half g_w1t[HID * KDIM];          // W1^T as fp16, [n][k]
__device__ uint4  g_bfrag[8192];              // B in mma-fragment order (128KB)
__device__ __half g_xh[(size_t)NROWS * KDIM]; // fp16 copy of x (written by k_scores)
__device__ int    g_segstart[NSEG + 1];

// ---------------- helpers ----------------------------------------------------
static __device__ __forceinline__ uint32_t smem_u32(const void* p) {
    uint32_t a;
    asm("{ .reg .u64 t; cvta.to.shared.u64 t, %1; cvt.u32.u64 %0, t; }"
        : "=r"(a) : "l"(p));
    return a;
}

static __device__ __forceinline__ void ldsm_x4(uint32_t a, uint32_t& r0, uint32_t& r1,
                                               uint32_t& r2, uint32_t& r3) {
    asm volatile("ldmatrix.sync.aligned.m8n8.x4.shared.b16 {%0,%1,%2,%3}, [%4];"
                 : "=r"(r0), "=r"(r1), "=r"(r2), "=r"(r3) : "r"(a));
}

static __device__ __forceinline__ void mma_f16(float* c,
                                               uint32_t a0, uint32_t a1, uint32_t a2, uint32_t a3,
                                               uint32_t b0, uint32_t b1) {
    asm volatile("mma.sync.aligned.m16n8k16.row.col.f32.f16.f16.f32 "
                 "{%0,%1,%2,%3}, {%4,%5,%6,%7}, {%8,%9}, {%0,%1,%2,%3};"
                 : "+f"(c[0]), "+f"(c[1]), "+f"(c[2]), "+f"(c[3])
                 : "r"(a0), "r"(a1), "r"(a2), "r"(a3), "r"(b0), "r"(b1));
}

static __device__ __forceinline__ uint32_t pack_h2(float a, float b) {
    __half2 h = __floats2half2_rn(a, b);
    return *(uint32_t*)&h;
}

// ---------------- kernel 1: W1^T -> fp16  +  boundary scan -------------------
__global__ void k_prep(const float* __restrict__ W1,
                       const void* __restrict__ batch_raw) {
    if (blockIdx.x < 256) {
        int k = blockIdx.x, n = threadIdx.x;
        g_w1t[n * KDIM + k] = __float2half_rn(W1[k * HID + n]);
        return;
    }
    const int* b32 = (const int*)batch_raw;
    const long long* b64 = (const long long*)batch_raw;
    bool is64 = (b32[NROWS - 1] == 0) && (b32[NROWS - 3] == 0) &&
                (b32[NROWS - 5] == 0) && (b32[NROWS - 7] == 0);
    int tid = (blockIdx.x - 256) * 256 + threadIdx.x;   // 0..65535
    #pragma unroll
    for (int q = 0; q < 4; q++) {
        int i = tid * 4 + q;
        if (i >= NROWS) break;
        int v = is64 ? (int)b64[i] : b32[i];
        if (i == 0) {
            for (int g = 0; g <= v; g++) g_segstart[g] = 0;
        }
        if (i == NROWS - 1) {
            for (int g = v + 1; g <= NSEG; g++) g_segstart[g] = NROWS;
        } else {
            int v1 = is64 ? (int)b64[i + 1] : b32[i + 1];
            for (int g = v + 1; g <= v1; g++) g_segstart[g] = i + 1;
        }
    }
}

// ---------------- kernel 2: B -> mma-fragment order --------------------------
// One block per 64-row n-chunk. Reuses scores' exact staging+ldsm path so the
// fragment layout is identical by construction.
__global__ void k_frag() {
    __shared__ char smem[32768];
    uint32_t sb = smem_u32(smem);
    int tid = threadIdx.x, wid = tid >> 5, lid = tid & 31;
    int ch = blockIdx.x;
    const uint4* wp = (const uint4*)g_w1t;
    #pragma unroll
    for (int i = 0; i < 8; i++) {
        int cid = tid + i * 256;
        int nl = cid >> 5, c = cid & 31;
        *(uint4*)(smem + nl * 512 + ((c ^ (nl & 7)) << 4)) = wp[ch * 2048 + cid];
    }
    __syncthreads();
    int nw = wid & 1;
    int j = lid >> 3, r8 = lid & 7;
    int bc0 = j & 1;
    int nloc = nw * 32 + ((j >> 1) << 3) + r8;
    int bnm = nloc & 7;
    uint32_t boff0 = nloc * 512;
    #pragma unroll
    for (int i = 0; i < 4; i++) {
        int ks = (wid >> 1) * 4 + i;
        uint32_t so = (uint32_t)(((2 * ks + bc0) ^ bnm) << 4);
        uint32_t b0[4], b1r[4];
        ldsm_x4(sb + boff0 + so,        b0[0], b0[1], b0[2], b0[3]);
        ldsm_x4(sb + boff0 + 8192 + so, b1r[0], b1r[1], b1r[2], b1r[3]);
        size_t base = ((size_t)(nw * 4 + ch) * 16 + ks) * 64;
        g_bfrag[base + lid]      = make_uint4(b0[0], b0[1], b0[2], b0[3]);
        g_bfrag[base + 32 + lid] = make_uint4(b1r[0], b1r[1], b1r[2], b1r[3]);
    }
}

// ---------------- kernel 3: scores, barrier-free mainloop --------------------
// Per CTA: M=128 rows, N=256 in 4 chunks of 64, K=256. B via fragment LDGs.
#define SM_A   0          // 128 x 256 fp16, swizzled           (65536)
#define SM_SC  65536      // 128 f32 partial scores             (512)
#define SM_B1  66048      // 256 f32                            (1024)
#define SM_W2  67072      // 256 f32                            (1024)
#define SMEM_SCORES_TOTAL 68096

__global__ void __launch_bounds__(256, 2)
k_scores(const float* __restrict__ x, const float* __restrict__ b1,
         const float* __restrict__ W2, const float* __restrict__ b2) {
    extern __shared__ char smem[];
    uint32_t sb = smem_u32(smem);
    int tid = threadIdx.x, wid = tid >> 5, lid = tid & 31;
    size_t rowbase = (size_t)blockIdx.x * 128;
    int mw = wid & 3, nw = wid >> 2;              // warp grid: 4 (M) x 2 (N)

    // stage constants, zero score accumulator
    if (tid < 128) ((float*)(smem + SM_SC))[tid] = 0.f;
    ((float*)(smem + SM_B1))[tid] = b1[tid];
    ((float*)(smem + SM_W2))[tid] = W2[tid];

    // ---- stage A tile: 128x256 f32 -> fp16, swizzled; also write g_xh ----
    {
        const float4* xp = (const float4*)(x + rowbase * 256);
        uint4* xh_out = (uint4*)(g_xh + rowbase * 256);
        #pragma unroll
        for (int i = 0; i < 16; i++) {
            int cid = tid + i * 256;              // 0..4095 chunks of 8 elems
            int row = cid >> 5, c = cid & 31;
            float4 v0 = __ldg(&xp[row * 64 + c * 2]);
            float4 v1 = __ldg(&xp[row * 64 + c * 2 + 1]);
            uint4 hv;
            hv.x = pack_h2(v0.x, v0.y);
            hv.y = pack_h2(v0.z, v0.w);
            hv.z = pack_h2(v1.x, v1.y);
            hv.w = pack_h2(v1.z, v1.w);
            uint32_t off = row * 512 + ((c ^ (row & 7)) << 4);
            *(uint4*)(smem + SM_A + off) = hv;
            xh_out[row * 32 + c] = hv;            // coalesced fp16 copy of x
        }
    }

    // ---- per-lane fragment address invariants ----
    int g = lid >> 2, t = lid & 3, r8 = lid & 7, j = lid >> 3;
    int arow = mw * 32 + (j & 1) * 8 + r8;
    uint32_t aoff0 = SM_A + arow * 512;
    int arm = arow & 7, ac0 = j >> 1;

    const float* smB1 = (const float*)(smem + SM_B1);
    const float* smW2 = (const float*)(smem + SM_W2);
    float part[4] = {0.f, 0.f, 0.f, 0.f};         // rows mw*32 + {g, g+8, 16+g, 24+g}

    __syncthreads();                              // A + constants staged

    for (int ch = 0; ch < 4; ch++) {
        const uint4* bp = g_bfrag + ((size_t)(nw * 4 + ch) * 16) * 64 + lid;

        float acc[2][4][4];
        #pragma unroll
        for (int a = 0; a < 2; a++)
            #pragma unroll
            for (int b = 0; b < 4; b++)
                #pragma unroll
                for (int cc = 0; cc < 4; cc++) acc[a][b][cc] = 0.f;

        #pragma unroll 8
        for (int ks = 0; ks < 16; ks++) {
            uint32_t sa = (uint32_t)(((2 * ks + ac0) ^ arm) << 4);
            uint32_t a0[4], a1[4];
            ldsm_x4(sb + aoff0 + sa,        a0[0], a0[1], a0[2], a0[3]);
            ldsm_x4(sb + aoff0 + 8192 + sa, a1[0], a1[1], a1[2], a1[3]);
            uint4 q0 = __ldg(bp + ks * 64);
            uint4 q1 = __ldg(bp + ks * 64 + 32);

            mma_f16(acc[0][0], a0[0], a0[1], a0[2], a0[3], q0.x, q0.y);
            mma_f16(acc[0][1], a0[0], a0[1], a0[2], a0[3], q0.z, q0.w);
            mma_f16(acc[0][2], a0[0], a0[1], a0[2], a0[3], q1.x, q1.y);
            mma_f16(acc[0][3], a0[0], a0[1], a0[2], a0[3], q1.z, q1.w);
            mma_f16(acc[1][0], a1[0], a1[1], a1[2], a1[3], q0.x, q0.y);
            mma_f16(acc[1][1], a1[0], a1[1], a1[2], a1[3], q0.z, q0.w);
            mma_f16(acc[1][2], a1[0], a1[1], a1[2], a1[3], q1.x, q1.y);
            mma_f16(acc[1][3], a1[0], a1[1], a1[2], a1[3], q1.z, q1.w);
        }

        // chunk epilogue: fold h -> relu(h + b1) . W2 into per-row partials
        int colb = ch * 64 + nw * 32 + 2 * t;
        #pragma unroll
        for (int nt = 0; nt < 4; nt++) {
            float bv0 = smB1[colb + nt * 8],     bv1 = smB1[colb + nt * 8 + 1];
            float wv0 = smW2[colb + nt * 8],     wv1 = smW2[colb + nt * 8 + 1];
            #pragma unroll
            for (int mt = 0; mt < 2; mt++) {
                part[mt * 2 + 0] += fmaxf(acc[mt][nt][0] + bv0, 0.f) * wv0
                                  + fmaxf(acc[mt][nt][1] + bv1, 0.f) * wv1;
                part[mt * 2 + 1] += fmaxf(acc[mt][nt][2] + bv0, 0.f) * wv0
                                  + fmaxf(acc[mt][nt][3] + bv1, 0.f) * wv1;
            }
        }
    }

    // reduce over the 4 lanes (t) that share each row
    #pragma unroll
    for (int p = 0; p < 4; p++) {
        part[p] += __shfl_xor_sync(0xffffffffu, part[p], 1);
        part[p] += __shfl_xor_sync(0xffffffffu, part[p], 2);
    }
    if (t == 0) {
        float* sc = (float*)(smem + SM_SC);
        atomicAdd(&sc[mw * 32 + g],      part[0]);
        atomicAdd(&sc[mw * 32 + 8 + g],  part[1]);
        atomicAdd(&sc[mw * 32 + 16 + g], part[2]);
        atomicAdd(&sc[mw * 32 + 24 + g], part[3]);
    }
    __syncthreads();
    if (tid < 128)
        g_scores[rowbase + tid] = ((float*)(smem + SM_SC))[tid] + __ldg(b2);
}

// ---------------- kernel 4: segment softmax + weighted pooling (fp16 x) -----
// 256 threads = 8 row-groups x 32 column-lanes; each lane loads uint4 (8 cols).
__global__ void __launch_bounds__(256)
k_pool(float* __restrict__ out) {
    __shared__ float wbuf[1024];
    __shared__ float red[256];
    __shared__ float accs[8][256];      // [row group][col]
    int g = blockIdx.x, t = threadIdx.x;
    int rg = t >> 5;                    // row group 0..7
    int cl = t & 31;                    // column lane: cols cl*8 .. cl*8+7
    int s0 = g_segstart[g], s1 = g_segstart[g + 1];

    // segment max, clamped at >= 0 (scatter-amax-into-zeros semantics)
    float m = 0.f;
    for (int i = s0 + t; i < s1; i += 256) m = fmaxf(m, g_scores[i]);
    red[t] = m; __syncthreads();
    #pragma unroll
    for (int st = 128; st > 0; st >>= 1) {
        if (t < st) red[t] = fmaxf(red[t], red[t + st]);
        __syncthreads();
    }
    m = red[0]; __syncthreads();

    float den = 0.f;
    float ac[8] = {0.f, 0.f, 0.f, 0.f, 0.f, 0.f, 0.f, 0.f};
    const uint4* xh4 = (const uint4*)g_xh;          // 32 uint4 per row
    for (int base = s0; base < s1; base += 1024) {
        int n = min(1024, s1 - base);
        for (int i = t; i < n; i += 256) {
            float e = __expf(g_scores[base + i] - m);
            wbuf[i] = e;
            den += e;
        }
        __syncthreads();
        const uint4* xb = xh4 + (size_t)base * 32 + cl;
        int i = rg;
        for (; i + 24 < n; i += 32) {               // rows i, i+8, i+16, i+24
            uint4 v0 = xb[(size_t)(i +  0) * 32];
            uint4 v1 = xb[(size_t)(i +  8) * 32];
            uint4 v2 = xb[(size_t)(i + 16) * 32];
            uint4 v3 = xb[(size_t)(i + 24) * 32];
            float w0 = wbuf[i], w1 = wbuf[i + 8], w2 = wbuf[i + 16], w3 = wbuf[i + 24];
            #pragma unroll
            for (int h = 0; h < 4; h++) {
                float2 p0 = __half22float2(*(((const __half2*)&v0) + h));
                float2 p1 = __half22float2(*(((const __half2*)&v1) + h));
                float2 p2 = __half22float2(*(((const __half2*)&v2) + h));
                float2 p3 = __half22float2(*(((const __half2*)&v3) + h));
                ac[2*h]   = fmaf(p0.x, w0, ac[2*h]);
                ac[2*h+1] = fmaf(p0.y, w0, ac[2*h+1]);
                ac[2*h]   = fmaf(p1.x, w1, ac[2*h]);
                ac[2*h+1] = fmaf(p1.y, w1, ac[2*h+1]);
                ac[2*h]   = fmaf(p2.x, w2, ac[2*h]);
                ac[2*h+1] = fmaf(p2.y, w2, ac[2*h+1]);
                ac[2*h]   = fmaf(p3.x, w3, ac[2*h]);
                ac[2*h+1] = fmaf(p3.y, w3, ac[2*h+1]);
            }
        }
        for (; i < n; i += 8) {
            uint4 v = xb[(size_t)i * 32];
            float w = wbuf[i];
            #pragma unroll
            for (int h = 0; h < 4; h++) {
                float2 p = __half22float2(*(((const __half2*)&v) + h));
                ac[2*h]   = fmaf(p.x, w, ac[2*h]);
                ac[2*h+1] = fmaf(p.y, w, ac[2*h+1]);
            }
        }
        __syncthreads();
    }

    // reduce denominator
    red[t] = den; __syncthreads();
    #pragma unroll
    for (int st = 128; st > 0; st >>= 1) {
        if (t < st) red[t] += red[t + st];
        __syncthreads();
    }
    den = red[0] + 1e-9f;
    __syncthreads();

    // combine row-group partials: accs[rg][col]
    #pragma unroll
    for (int h = 0; h < 8; h++) accs[rg][cl * 8 + h] = ac[h];
    __syncthreads();
    float s = 0.f;
    #pragma unroll
    for (int r = 0; r < 8; r++) s += accs[r][t];
    out[g * 256 + t] = s / den;
}

// ---------------- launch ----------------------------------------------------
extern "C" void kernel_launch(void* const* d_in, const int* in_sizes, int n_in,
                              void* d_out, int out_size) {
    const float* x = 0; const float* W1 = 0; const float* b1 = 0;
    const float* W2 = 0; const float* b2 = 0; const void* batch = 0;
    for (int i = 0; i < n_in; i++) {
        switch (in_sizes[i]) {
            case 67108864: x = (const float*)d_in[i]; break;
            case 65536:    W1 = (const float*)d_in[i]; break;
            case 262144:   batch = d_in[i]; break;
            case 1:        b2 = (const float*)d_in[i]; break;
            case 256:
                if (!b1) b1 = (const float*)d_in[i];
                else     W2 = (const float*)d_in[i];
                break;
            default: break;
        }
    }
    if (!x)     x     = (const float*)d_in[0];
    if (!W1)    W1    = (const float*)d_in[1];
    if (!b1)    b1    = (const float*)d_in[2];
    if (!W2)    W2    = (const float*)d_in[3];
    if (!b2)    b2    = (const float*)d_in[4];
    if (!batch) batch = d_in[5];

    cudaFuncSetAttribute(k_scores, cudaFuncAttributeMaxDynamicSharedMemorySize,
                         SMEM_SCORES_TOTAL);

    k_prep<<<512, 256>>>(W1, batch);
    k_frag<<<4, 256>>>();
    k_scores<<<NROWS / 128, 256, SMEM_SCORES_TOTAL>>>(x, b1, W2, b2);
    k_pool<<<NSEG, 256>>>((float*)d_out);
}

// round 14
// speedup vs baseline: 1.6352x; 1.0127x over previous
#include <cuda_runtime.h>
#include <cuda_fp16.h>
#include <cstdint>

#define NROWS   262144
#define NSEG    1024
#define HID     256
#define KDIM    256

// ---------------- scratch (device globals: no allocations allowed) ----------
__device__ float  g_scores[NROWS];
__device__ __half g_w1t[HID * KDIM];          // W1^T as fp16, [n][k]
__device__ uint4  g_bfrag[8192];              // B in mma-fragment order (128KB)
__device__ __half g_xh[(size_t)NROWS * KDIM]; // fp16 copy of x (written by k_scores)
__device__ int    g_segstart[NSEG + 1];

// ---------------- helpers ----------------------------------------------------
static __device__ __forceinline__ uint32_t smem_u32(const void* p) {
    uint32_t a;
    asm("{ .reg .u64 t; cvta.to.shared.u64 t, %1; cvt.u32.u64 %0, t; }"
        : "=r"(a) : "l"(p));
    return a;
}

static __device__ __forceinline__ void ldsm_x4(uint32_t a, uint32_t& r0, uint32_t& r1,
                                               uint32_t& r2, uint32_t& r3) {
    asm volatile("ldmatrix.sync.aligned.m8n8.x4.shared.b16 {%0,%1,%2,%3}, [%4];"
                 : "=r"(r0), "=r"(r1), "=r"(r2), "=r"(r3) : "r"(a));
}

static __device__ __forceinline__ void mma_f16(float* c,
                                               uint32_t a0, uint32_t a1, uint32_t a2, uint32_t a3,
                                               uint32_t b0, uint32_t b1) {
    asm volatile("mma.sync.aligned.m16n8k16.row.col.f32.f16.f16.f32 "
                 "{%0,%1,%2,%3}, {%4,%5,%6,%7}, {%8,%9}, {%0,%1,%2,%3};"
                 : "+f"(c[0]), "+f"(c[1]), "+f"(c[2]), "+f"(c[3])
                 : "r"(a0), "r"(a1), "r"(a2), "r"(a3), "r"(b0), "r"(b1));
}

static __device__ __forceinline__ uint32_t pack_h2(float a, float b) {
    __half2 h = __floats2half2_rn(a, b);
    return *(uint32_t*)&h;
}

// ---------------- kernel 1: W1^T -> fp16  +  boundary scan -------------------
__global__ void k_prep(const float* __restrict__ W1,
                       const void* __restrict__ batch_raw) {
    if (blockIdx.x < 256) {
        int k = blockIdx.x, n = threadIdx.x;
        g_w1t[n * KDIM + k] = __float2half_rn(W1[k * HID + n]);
        return;
    }
    const int* b32 = (const int*)batch_raw;
    const long long* b64 = (const long long*)batch_raw;
    bool is64 = (b32[NROWS - 1] == 0) && (b32[NROWS - 3] == 0) &&
                (b32[NROWS - 5] == 0) && (b32[NROWS - 7] == 0);
    int tid = (blockIdx.x - 256) * 256 + threadIdx.x;   // 0..65535
    #pragma unroll
    for (int q = 0; q < 4; q++) {
        int i = tid * 4 + q;
        if (i >= NROWS) break;
        int v = is64 ? (int)b64[i] : b32[i];
        if (i == 0) {
            for (int g = 0; g <= v; g++) g_segstart[g] = 0;
        }
        if (i == NROWS - 1) {
            for (int g = v + 1; g <= NSEG; g++) g_segstart[g] = NROWS;
        } else {
            int v1 = is64 ? (int)b64[i + 1] : b32[i + 1];
            for (int g = v + 1; g <= v1; g++) g_segstart[g] = i + 1;
        }
    }
}

// ---------------- kernel 2: B -> mma-fragment order --------------------------
__global__ void k_frag() {
    __shared__ char smem[32768];
    uint32_t sb = smem_u32(smem);
    int tid = threadIdx.x, wid = tid >> 5, lid = tid & 31;
    int ch = blockIdx.x;
    const uint4* wp = (const uint4*)g_w1t;
    #pragma unroll
    for (int i = 0; i < 8; i++) {
        int cid = tid + i * 256;
        int nl = cid >> 5, c = cid & 31;
        *(uint4*)(smem + nl * 512 + ((c ^ (nl & 7)) << 4)) = wp[ch * 2048 + cid];
    }
    __syncthreads();
    int nw = wid & 1;
    int j = lid >> 3, r8 = lid & 7;
    int bc0 = j & 1;
    int nloc = nw * 32 + ((j >> 1) << 3) + r8;
    int bnm = nloc & 7;
    uint32_t boff0 = nloc * 512;
    #pragma unroll
    for (int i = 0; i < 4; i++) {
        int ks = (wid >> 1) * 4 + i;
        uint32_t so = (uint32_t)(((2 * ks + bc0) ^ bnm) << 4);
        uint32_t b0[4], b1r[4];
        ldsm_x4(sb + boff0 + so,        b0[0], b0[1], b0[2], b0[3]);
        ldsm_x4(sb + boff0 + 8192 + so, b1r[0], b1r[1], b1r[2], b1r[3]);
        size_t base = ((size_t)(nw * 4 + ch) * 16 + ks) * 64;
        g_bfrag[base + lid]      = make_uint4(b0[0], b0[1], b0[2], b0[3]);
        g_bfrag[base + 32 + lid] = make_uint4(b1r[0], b1r[1], b1r[2], b1r[3]);
    }
}

// ---------------- kernel 3: scores, barrier-free mainloop (LOCKED) -----------
#define SM_A   0          // 128 x 256 fp16, swizzled           (65536)
#define SM_SC  65536      // 128 f32 partial scores             (512)
#define SM_B1  66048      // 256 f32                            (1024)
#define SM_W2  67072      // 256 f32                            (1024)
#define SMEM_SCORES_TOTAL 68096

__global__ void __launch_bounds__(256, 2)
k_scores(const float* __restrict__ x, const float* __restrict__ b1,
         const float* __restrict__ W2, const float* __restrict__ b2) {
    extern __shared__ char smem[];
    uint32_t sb = smem_u32(smem);
    int tid = threadIdx.x, wid = tid >> 5, lid = tid & 31;
    size_t rowbase = (size_t)blockIdx.x * 128;
    int mw = wid & 3, nw = wid >> 2;              // warp grid: 4 (M) x 2 (N)

    // stage constants, zero score accumulator
    if (tid < 128) ((float*)(smem + SM_SC))[tid] = 0.f;
    ((float*)(smem + SM_B1))[tid] = b1[tid];
    ((float*)(smem + SM_W2))[tid] = W2[tid];

    // ---- stage A tile: 128x256 f32 -> fp16, swizzled; also write g_xh ----
    {
        const float4* xp = (const float4*)(x + rowbase * 256);
        uint4* xh_out = (uint4*)(g_xh + rowbase * 256);
        #pragma unroll
        for (int i = 0; i < 16; i++) {
            int cid = tid + i * 256;              // 0..4095 chunks of 8 elems
            int row = cid >> 5, c = cid & 31;
            float4 v0 = __ldg(&xp[row * 64 + c * 2]);
            float4 v1 = __ldg(&xp[row * 64 + c * 2 + 1]);
            uint4 hv;
            hv.x = pack_h2(v0.x, v0.y);
            hv.y = pack_h2(v0.z, v0.w);
            hv.z = pack_h2(v1.x, v1.y);
            hv.w = pack_h2(v1.z, v1.w);
            uint32_t off = row * 512 + ((c ^ (row & 7)) << 4);
            *(uint4*)(smem + SM_A + off) = hv;
            xh_out[row * 32 + c] = hv;            // coalesced fp16 copy of x
        }
    }

    // ---- per-lane fragment address invariants ----
    int g = lid >> 2, t = lid & 3, r8 = lid & 7, j = lid >> 3;
    int arow = mw * 32 + (j & 1) * 8 + r8;
    uint32_t aoff0 = SM_A + arow * 512;
    int arm = arow & 7, ac0 = j >> 1;

    const float* smB1 = (const float*)(smem + SM_B1);
    const float* smW2 = (const float*)(smem + SM_W2);
    float part[4] = {0.f, 0.f, 0.f, 0.f};         // rows mw*32 + {g, g+8, 16+g, 24+g}

    __syncthreads();                              // A + constants staged

    for (int ch = 0; ch < 4; ch++) {
        const uint4* bp = g_bfrag + ((size_t)(nw * 4 + ch) * 16) * 64 + lid;

        float acc[2][4][4];
        #pragma unroll
        for (int a = 0; a < 2; a++)
            #pragma unroll
            for (int b = 0; b < 4; b++)
                #pragma unroll
                for (int cc = 0; cc < 4; cc++) acc[a][b][cc] = 0.f;

        #pragma unroll 8
        for (int ks = 0; ks < 16; ks++) {
            uint32_t sa = (uint32_t)(((2 * ks + ac0) ^ arm) << 4);
            uint32_t a0[4], a1[4];
            ldsm_x4(sb + aoff0 + sa,        a0[0], a0[1], a0[2], a0[3]);
            ldsm_x4(sb + aoff0 + 8192 + sa, a1[0], a1[1], a1[2], a1[3]);
            uint4 q0 = __ldg(bp + ks * 64);
            uint4 q1 = __ldg(bp + ks * 64 + 32);

            mma_f16(acc[0][0], a0[0], a0[1], a0[2], a0[3], q0.x, q0.y);
            mma_f16(acc[0][1], a0[0], a0[1], a0[2], a0[3], q0.z, q0.w);
            mma_f16(acc[0][2], a0[0], a0[1], a0[2], a0[3], q1.x, q1.y);
            mma_f16(acc[0][3], a0[0], a0[1], a0[2], a0[3], q1.z, q1.w);
            mma_f16(acc[1][0], a1[0], a1[1], a1[2], a1[3], q0.x, q0.y);
            mma_f16(acc[1][1], a1[0], a1[1], a1[2], a1[3], q0.z, q0.w);
            mma_f16(acc[1][2], a1[0], a1[1], a1[2], a1[3], q1.x, q1.y);
            mma_f16(acc[1][3], a1[0], a1[1], a1[2], a1[3], q1.z, q1.w);
        }

        // chunk epilogue: fold h -> relu(h + b1) . W2 into per-row partials
        int colb = ch * 64 + nw * 32 + 2 * t;
        #pragma unroll
        for (int nt = 0; nt < 4; nt++) {
            float bv0 = smB1[colb + nt * 8],     bv1 = smB1[colb + nt * 8 + 1];
            float wv0 = smW2[colb + nt * 8],     wv1 = smW2[colb + nt * 8 + 1];
            #pragma unroll
            for (int mt = 0; mt < 2; mt++) {
                part[mt * 2 + 0] += fmaxf(acc[mt][nt][0] + bv0, 0.f) * wv0
                                  + fmaxf(acc[mt][nt][1] + bv1, 0.f) * wv1;
                part[mt * 2 + 1] += fmaxf(acc[mt][nt][2] + bv0, 0.f) * wv0
                                  + fmaxf(acc[mt][nt][3] + bv1, 0.f) * wv1;
            }
        }
    }

    // reduce over the 4 lanes (t) that share each row
    #pragma unroll
    for (int p = 0; p < 4; p++) {
        part[p] += __shfl_xor_sync(0xffffffffu, part[p], 1);
        part[p] += __shfl_xor_sync(0xffffffffu, part[p], 2);
    }
    if (t == 0) {
        float* sc = (float*)(smem + SM_SC);
        atomicAdd(&sc[mw * 32 + g],      part[0]);
        atomicAdd(&sc[mw * 32 + 8 + g],  part[1]);
        atomicAdd(&sc[mw * 32 + 16 + g], part[2]);
        atomicAdd(&sc[mw * 32 + 24 + g], part[3]);
    }
    __syncthreads();
    if (tid < 128)
        g_scores[rowbase + tid] = ((float*)(smem + SM_SC))[tid] + __ldg(b2);
}

// ---------------- kernel 4: segment softmax + weighted pooling (fp16 x) -----
// 256 threads = 8 row-groups x 32 column-lanes; 8 uint4 loads in flight.
__global__ void __launch_bounds__(256)
k_pool(float* __restrict__ out) {
    __shared__ float wbuf[1024];
    __shared__ float red[256];
    __shared__ float accs[8][256];      // [row group][col]
    int g = blockIdx.x, t = threadIdx.x;
    int rg = t >> 5;                    // row group 0..7
    int cl = t & 31;                    // column lane: cols cl*8 .. cl*8+7
    int s0 = g_segstart[g], s1 = g_segstart[g + 1];

    // segment max, clamped at >= 0 (scatter-amax-into-zeros semantics)
    float m = 0.f;
    for (int i = s0 + t; i < s1; i += 256) m = fmaxf(m, g_scores[i]);
    red[t] = m; __syncthreads();
    #pragma unroll
    for (int st = 128; st > 0; st >>= 1) {
        if (t < st) red[t] = fmaxf(red[t], red[t + st]);
        __syncthreads();
    }
    m = red[0]; __syncthreads();

    float den = 0.f;
    float ac[8] = {0.f, 0.f, 0.f, 0.f, 0.f, 0.f, 0.f, 0.f};
    const uint4* xh4 = (const uint4*)g_xh;          // 32 uint4 per row
    for (int base = s0; base < s1; base += 1024) {
        int n = min(1024, s1 - base);
        for (int i = t; i < n; i += 256) {
            float e = __expf(g_scores[base + i] - m);
            wbuf[i] = e;
            den += e;
        }
        __syncthreads();
        const uint4* xb = xh4 + (size_t)base * 32 + cl;
        int i = rg;
        for (; i + 56 < n; i += 64) {   // 8 rows: i, i+8, ..., i+56 in flight
            uint4 v0 = xb[(size_t)(i +  0) * 32];
            uint4 v1 = xb[(size_t)(i +  8) * 32];
            uint4 v2 = xb[(size_t)(i + 16) * 32];
            uint4 v3 = xb[(size_t)(i + 24) * 32];
            uint4 v4 = xb[(size_t)(i + 32) * 32];
            uint4 v5 = xb[(size_t)(i + 40) * 32];
            uint4 v6 = xb[(size_t)(i + 48) * 32];
            uint4 v7 = xb[(size_t)(i + 56) * 32];
            float w0 = wbuf[i],      w1 = wbuf[i + 8];
            float w2 = wbuf[i + 16], w3 = wbuf[i + 24];
            float w4 = wbuf[i + 32], w5 = wbuf[i + 40];
            float w6 = wbuf[i + 48], w7 = wbuf[i + 56];
            #pragma unroll
            for (int h = 0; h < 4; h++) {
                float2 p;
                p = __half22float2(*(((const __half2*)&v0) + h));
                ac[2*h] = fmaf(p.x, w0, ac[2*h]); ac[2*h+1] = fmaf(p.y, w0, ac[2*h+1]);
                p = __half22float2(*(((const __half2*)&v1) + h));
                ac[2*h] = fmaf(p.x, w1, ac[2*h]); ac[2*h+1] = fmaf(p.y, w1, ac[2*h+1]);
                p = __half22float2(*(((const __half2*)&v2) + h));
                ac[2*h] = fmaf(p.x, w2, ac[2*h]); ac[2*h+1] = fmaf(p.y, w2, ac[2*h+1]);
                p = __half22float2(*(((const __half2*)&v3) + h));
                ac[2*h] = fmaf(p.x, w3, ac[2*h]); ac[2*h+1] = fmaf(p.y, w3, ac[2*h+1]);
                p = __half22float2(*(((const __half2*)&v4) + h));
                ac[2*h] = fmaf(p.x, w4, ac[2*h]); ac[2*h+1] = fmaf(p.y, w4, ac[2*h+1]);
                p = __half22float2(*(((const __half2*)&v5) + h));
                ac[2*h] = fmaf(p.x, w5, ac[2*h]); ac[2*h+1] = fmaf(p.y, w5, ac[2*h+1]);
                p = __half22float2(*(((const __half2*)&v6) + h));
                ac[2*h] = fmaf(p.x, w6, ac[2*h]); ac[2*h+1] = fmaf(p.y, w6, ac[2*h+1]);
                p = __half22float2(*(((const __half2*)&v7) + h));
                ac[2*h] = fmaf(p.x, w7, ac[2*h]); ac[2*h+1] = fmaf(p.y, w7, ac[2*h+1]);
            }
        }
        for (; i < n; i += 8) {
            uint4 v = xb[(size_t)i * 32];
            float w = wbuf[i];
            #pragma unroll
            for (int h = 0; h < 4; h++) {
                float2 p = __half22float2(*(((const __half2*)&v) + h));
                ac[2*h]   = fmaf(p.x, w, ac[2*h]);
                ac[2*h+1] = fmaf(p.y, w, ac[2*h+1]);
            }
        }
        __syncthreads();
    }

    // reduce denominator
    red[t] = den; __syncthreads();
    #pragma unroll
    for (int st = 128; st > 0; st >>= 1) {
        if (t < st) red[t] += red[t + st];
        __syncthreads();
    }
    den = red[0] + 1e-9f;
    __syncthreads();

    // combine row-group partials: accs[rg][col]
    #pragma unroll
    for (int h = 0; h < 8; h++) accs[rg][cl * 8 + h] = ac[h];
    __syncthreads();
    float s = 0.f;
    #pragma unroll
    for (int r = 0; r < 8; r++) s += accs[r][t];
    out[g * 256 + t] = s / den;
}

// ---------------- launch ----------------------------------------------------
extern "C" void kernel_launch(void* const* d_in, const int* in_sizes, int n_in,
                              void* d_out, int out_size) {
    const float* x = 0; const float* W1 = 0; const float* b1 = 0;
    const float* W2 = 0; const float* b2 = 0; const void* batch = 0;
    for (int i = 0; i < n_in; i++) {
        switch (in_sizes[i]) {
            case 67108864: x = (const float*)d_in[i]; break;
            case 65536:    W1 = (const float*)d_in[i]; break;
            case 262144:   batch = d_in[i]; break;
            case 1:        b2 = (const float*)d_in[i]; break;
            case 256:
                if (!b1) b1 = (const float*)d_in[i];
                else     W2 = (const float*)d_in[i];
                break;
            default: break;
        }
    }
    if (!x)     x     = (const float*)d_in[0];
    if (!W1)    W1    = (const float*)d_in[1];
    if (!b1)    b1    = (const float*)d_in[2];
    if (!W2)    W2    = (const float*)d_in[3];
    if (!b2)    b2    = (const float*)d_in[4];
    if (!batch) batch = d_in[5];

    cudaFuncSetAttribute(k_scores, cudaFuncAttributeMaxDynamicSharedMemorySize,
                         SMEM_SCORES_TOTAL);

    k_prep<<<512, 256>>>(W1, batch);
    k_frag<<<4, 256>>>();
    k_scores<<<NROWS / 128, 256, SMEM_SCORES_TOTAL>>>(x, b1, W2, b2);
    k_pool<<<NSEG, 256>>>((float*)d_out);
}

// round 15
// speedup vs baseline: 1.6358x; 1.0004x over previous
#include <cuda_runtime.h>
#include <cuda_fp16.h>
#include <cstdint>

#define NROWS   262144
#define NSEG    1024
#define HID     256
#define KDIM    256

// ---------------- scratch (device globals: no allocations allowed) ----------
__device__ float  g_scores[NROWS];
__device__ uint4  g_bfrag[8192];              // B in mma-fragment order (128KB)
__device__ __half g_xh[(size_t)NROWS * KDIM]; // fp16 copy of x (written by k_scores)
__device__ int    g_segstart[NSEG + 1];

// ---------------- helpers ----------------------------------------------------
static __device__ __forceinline__ uint32_t smem_u32(const void* p) {
    uint32_t a;
    asm("{ .reg .u64 t; cvta.to.shared.u64 t, %1; cvt.u32.u64 %0, t; }"
        : "=r"(a) : "l"(p));
    return a;
}

static __device__ __forceinline__ void ldsm_x4(uint32_t a, uint32_t& r0, uint32_t& r1,
                                               uint32_t& r2, uint32_t& r3) {
    asm volatile("ldmatrix.sync.aligned.m8n8.x4.shared.b16 {%0,%1,%2,%3}, [%4];"
                 : "=r"(r0), "=r"(r1), "=r"(r2), "=r"(r3) : "r"(a));
}

static __device__ __forceinline__ void mma_f16(float* c,
                                               uint32_t a0, uint32_t a1, uint32_t a2, uint32_t a3,
                                               uint32_t b0, uint32_t b1) {
    asm volatile("mma.sync.aligned.m16n8k16.row.col.f32.f16.f16.f32 "
                 "{%0,%1,%2,%3}, {%4,%5,%6,%7}, {%8,%9}, {%0,%1,%2,%3};"
                 : "+f"(c[0]), "+f"(c[1]), "+f"(c[2]), "+f"(c[3])
                 : "r"(a0), "r"(a1), "r"(a2), "r"(a3), "r"(b0), "r"(b1));
}

static __device__ __forceinline__ uint32_t pack_h2(float a, float b) {
    __half2 h = __floats2half2_rn(a, b);
    return *(uint32_t*)&h;
}

static __device__ __forceinline__ void cp16(uint32_t dst, const void* src) {
    asm volatile("cp.async.cg.shared.global [%0], [%1], 16;"
                 :: "r"(dst), "l"(src) : "memory");
}
#define CP_COMMIT() asm volatile("cp.async.commit_group;" ::: "memory")
#define CP_WAIT(N)  asm volatile("cp.async.wait_group %0;" :: "n"(N) : "memory")

// ---------------- kernel 1: B fragments (from W1) + boundary scan ------------
// blocks 0..3: build g_bfrag directly from W1 (same smem image as before).
// blocks 4..259: segment boundaries via adjacent-diff scan (batch sorted).
__global__ void k_prep(const float* __restrict__ W1,
                       const void* __restrict__ batch_raw) {
    int tid = threadIdx.x;
    if (blockIdx.x < 4) {
        __shared__ char fs[32768];
        uint32_t sb = smem_u32(fs);
        int wid = tid >> 5, lid = tid & 31;
        int ch = blockIdx.x;
        // stage 64 n-rows x 256 k as fp16, SW-swizzled (coalesced W1 reads)
        #pragma unroll
        for (int it = 0; it < 8; it++) {
            int idx = tid + it * 256;             // 0..2047
            int nl = idx & 63, c = idx >> 6;      // nl: n-local, c: k-chunk of 8
            int n = ch * 64 + nl;
            uint32_t h[4];
            #pragma unroll
            for (int qq = 0; qq < 4; qq++) {
                float v0 = W1[(c * 8 + 2 * qq) * 256 + n];
                float v1 = W1[(c * 8 + 2 * qq + 1) * 256 + n];
                h[qq] = pack_h2(v0, v1);
            }
            *(uint4*)(fs + nl * 512 + ((c ^ (nl & 7)) << 4)) =
                make_uint4(h[0], h[1], h[2], h[3]);
        }
        __syncthreads();
        int nw = wid & 1;
        int j = lid >> 3, r8 = lid & 7;
        int bc0 = j & 1;
        int nloc = nw * 32 + ((j >> 1) << 3) + r8;
        int bnm = nloc & 7;
        uint32_t boff0 = nloc * 512;
        #pragma unroll
        for (int i = 0; i < 4; i++) {
            int ks = (wid >> 1) * 4 + i;
            uint32_t so = (uint32_t)(((2 * ks + bc0) ^ bnm) << 4);
            uint32_t b0[4], b1r[4];
            ldsm_x4(sb + boff0 + so,        b0[0], b0[1], b0[2], b0[3]);
            ldsm_x4(sb + boff0 + 8192 + so, b1r[0], b1r[1], b1r[2], b1r[3]);
            size_t base = ((size_t)(nw * 4 + ch) * 16 + ks) * 64;
            g_bfrag[base + lid]      = make_uint4(b0[0], b0[1], b0[2], b0[3]);
            g_bfrag[base + 32 + lid] = make_uint4(b1r[0], b1r[1], b1r[2], b1r[3]);
        }
        return;
    }
    const int* b32 = (const int*)batch_raw;
    const long long* b64 = (const long long*)batch_raw;
    bool is64 = (b32[NROWS - 1] == 0) && (b32[NROWS - 3] == 0) &&
                (b32[NROWS - 5] == 0) && (b32[NROWS - 7] == 0);
    int gt = (blockIdx.x - 4) * 256 + tid;        // 0..65535
    #pragma unroll
    for (int q = 0; q < 4; q++) {
        int i = gt * 4 + q;
        if (i >= NROWS) break;
        int v = is64 ? (int)b64[i] : b32[i];
        if (i == 0) {
            for (int g = 0; g <= v; g++) g_segstart[g] = 0;
        }
        if (i == NROWS - 1) {
            for (int g = v + 1; g <= NSEG; g++) g_segstart[g] = NROWS;
        } else {
            int v1 = is64 ? (int)b64[i + 1] : b32[i + 1];
            for (int g = v + 1; g <= v1; g++) g_segstart[g] = i + 1;
        }
    }
}

// ---------------- kernel 2: scores, barrier-free mainloop (LOCKED) -----------
#define SM_A   0          // 128 x 256 fp16, swizzled           (65536)
#define SM_SC  65536      // 128 f32 partial scores             (512)
#define SM_B1  66048      // 256 f32                            (1024)
#define SM_W2  67072      // 256 f32                            (1024)
#define SMEM_SCORES_TOTAL 68096

__global__ void __launch_bounds__(256, 2)
k_scores(const float* __restrict__ x, const float* __restrict__ b1,
         const float* __restrict__ W2, const float* __restrict__ b2) {
    extern __shared__ char smem[];
    uint32_t sb = smem_u32(smem);
    int tid = threadIdx.x, wid = tid >> 5, lid = tid & 31;
    size_t rowbase = (size_t)blockIdx.x * 128;
    int mw = wid & 3, nw = wid >> 2;              // warp grid: 4 (M) x 2 (N)

    // stage constants, zero score accumulator
    if (tid < 128) ((float*)(smem + SM_SC))[tid] = 0.f;
    ((float*)(smem + SM_B1))[tid] = b1[tid];
    ((float*)(smem + SM_W2))[tid] = W2[tid];

    // ---- stage A tile: 128x256 f32 -> fp16, swizzled; also write g_xh ----
    {
        const float4* xp = (const float4*)(x + rowbase * 256);
        uint4* xh_out = (uint4*)(g_xh + rowbase * 256);
        #pragma unroll
        for (int i = 0; i < 16; i++) {
            int cid = tid + i * 256;              // 0..4095 chunks of 8 elems
            int row = cid >> 5, c = cid & 31;
            float4 v0 = __ldg(&xp[row * 64 + c * 2]);
            float4 v1 = __ldg(&xp[row * 64 + c * 2 + 1]);
            uint4 hv;
            hv.x = pack_h2(v0.x, v0.y);
            hv.y = pack_h2(v0.z, v0.w);
            hv.z = pack_h2(v1.x, v1.y);
            hv.w = pack_h2(v1.z, v1.w);
            uint32_t off = row * 512 + ((c ^ (row & 7)) << 4);
            *(uint4*)(smem + SM_A + off) = hv;
            xh_out[row * 32 + c] = hv;            // coalesced fp16 copy of x
        }
    }

    // ---- per-lane fragment address invariants ----
    int g = lid >> 2, t = lid & 3, r8 = lid & 7, j = lid >> 3;
    int arow = mw * 32 + (j & 1) * 8 + r8;
    uint32_t aoff0 = SM_A + arow * 512;
    int arm = arow & 7, ac0 = j >> 1;

    const float* smB1 = (const float*)(smem + SM_B1);
    const float* smW2 = (const float*)(smem + SM_W2);
    float part[4] = {0.f, 0.f, 0.f, 0.f};         // rows mw*32 + {g, g+8, 16+g, 24+g}

    __syncthreads();                              // A + constants staged

    for (int ch = 0; ch < 4; ch++) {
        const uint4* bp = g_bfrag + ((size_t)(nw * 4 + ch) * 16) * 64 + lid;

        float acc[2][4][4];
        #pragma unroll
        for (int a = 0; a < 2; a++)
            #pragma unroll
            for (int b = 0; b < 4; b++)
                #pragma unroll
                for (int cc = 0; cc < 4; cc++) acc[a][b][cc] = 0.f;

        #pragma unroll 8
        for (int ks = 0; ks < 16; ks++) {
            uint32_t sa = (uint32_t)(((2 * ks + ac0) ^ arm) << 4);
            uint32_t a0[4], a1[4];
            ldsm_x4(sb + aoff0 + sa,        a0[0], a0[1], a0[2], a0[3]);
            ldsm_x4(sb + aoff0 + 8192 + sa, a1[0], a1[1], a1[2], a1[3]);
            uint4 q0 = __ldg(bp + ks * 64);
            uint4 q1 = __ldg(bp + ks * 64 + 32);

            mma_f16(acc[0][0], a0[0], a0[1], a0[2], a0[3], q0.x, q0.y);
            mma_f16(acc[0][1], a0[0], a0[1], a0[2], a0[3], q0.z, q0.w);
            mma_f16(acc[0][2], a0[0], a0[1], a0[2], a0[3], q1.x, q1.y);
            mma_f16(acc[0][3], a0[0], a0[1], a0[2], a0[3], q1.z, q1.w);
            mma_f16(acc[1][0], a1[0], a1[1], a1[2], a1[3], q0.x, q0.y);
            mma_f16(acc[1][1], a1[0], a1[1], a1[2], a1[3], q0.z, q0.w);
            mma_f16(acc[1][2], a1[0], a1[1], a1[2], a1[3], q1.x, q1.y);
            mma_f16(acc[1][3], a1[0], a1[1], a1[2], a1[3], q1.z, q1.w);
        }

        // chunk epilogue: fold h -> relu(h + b1) . W2 into per-row partials
        int colb = ch * 64 + nw * 32 + 2 * t;
        #pragma unroll
        for (int nt = 0; nt < 4; nt++) {
            float bv0 = smB1[colb + nt * 8],     bv1 = smB1[colb + nt * 8 + 1];
            float wv0 = smW2[colb + nt * 8],     wv1 = smW2[colb + nt * 8 + 1];
            #pragma unroll
            for (int mt = 0; mt < 2; mt++) {
                part[mt * 2 + 0] += fmaxf(acc[mt][nt][0] + bv0, 0.f) * wv0
                                  + fmaxf(acc[mt][nt][1] + bv1, 0.f) * wv1;
                part[mt * 2 + 1] += fmaxf(acc[mt][nt][2] + bv0, 0.f) * wv0
                                  + fmaxf(acc[mt][nt][3] + bv1, 0.f) * wv1;
            }
        }
    }

    // reduce over the 4 lanes (t) that share each row
    #pragma unroll
    for (int p = 0; p < 4; p++) {
        part[p] += __shfl_xor_sync(0xffffffffu, part[p], 1);
        part[p] += __shfl_xor_sync(0xffffffffu, part[p], 2);
    }
    if (t == 0) {
        float* sc = (float*)(smem + SM_SC);
        atomicAdd(&sc[mw * 32 + g],      part[0]);
        atomicAdd(&sc[mw * 32 + 8 + g],  part[1]);
        atomicAdd(&sc[mw * 32 + 16 + g], part[2]);
        atomicAdd(&sc[mw * 32 + 24 + g], part[3]);
    }
    __syncthreads();
    if (tid < 128)
        g_scores[rowbase + tid] = ((float*)(smem + SM_SC))[tid] + __ldg(b2);
}

// ---------------- kernel 3: pooling with cp.async double buffer --------------
// dynamic smem: [0,32768) xbuf0, [32768,65536) xbuf1, [65536,+4096) wbuf,
// [69632,+1024) red, [70656,+8192) accs[8][256]  -> total 78848
#define P_WB   65536
#define P_RED  69632
#define P_ACC  70656
#define SMEM_POOL_TOTAL 78848

__global__ void __launch_bounds__(256)
k_pool(float* __restrict__ out) {
    extern __shared__ char ps[];
    uint32_t sbp = smem_u32(ps);
    float* wbuf = (float*)(ps + P_WB);
    float* red  = (float*)(ps + P_RED);
    float* accs = (float*)(ps + P_ACC);   // [8][256]
    int g = blockIdx.x, t = threadIdx.x;
    int rg = t >> 5, cl = t & 31;
    int s0 = g_segstart[g], s1 = g_segstart[g + 1];

    // segment max, clamped at >= 0 (scatter-amax-into-zeros semantics)
    float m = 0.f;
    for (int i = s0 + t; i < s1; i += 256) m = fmaxf(m, g_scores[i]);
    red[t] = m; __syncthreads();
    #pragma unroll
    for (int st = 128; st > 0; st >>= 1) {
        if (t < st) red[t] = fmaxf(red[t], red[t + st]);
        __syncthreads();
    }
    m = red[0]; __syncthreads();

    float den = 0.f;
    float ac[8] = {0.f, 0.f, 0.f, 0.f, 0.f, 0.f, 0.f, 0.f};
    const char* xbytes = (const char*)g_xh;

    for (int base = s0; base < s1; base += 1024) {
        int n = min(1024, s1 - base);
        for (int i = t; i < n; i += 256) {
            float e = __expf(g_scores[base + i] - m);
            wbuf[i] = e;
            den += e;
        }
        __syncthreads();                          // wbuf visible; prev buffers free

        int nsub = (n + 63) >> 6;
        // prefetch sub 0 into buf 0
        {
            int cnt = min(64, n) * 32;            // 16B units
            const char* src = xbytes + (size_t)base * 512;
            for (int idx = t; idx < cnt; idx += 256)
                cp16(sbp + idx * 16, src + (size_t)idx * 16);
            CP_COMMIT();
        }
        for (int s = 0; s < nsub; s++) {
            if (s > 0) __syncthreads();           // consumers of buf (s+1)&1 done
            if (s + 1 < nsub) {
                int r0n = (s + 1) * 64;
                int cnt = min(64, n - r0n) * 32;
                const char* src = xbytes + (size_t)(base + r0n) * 512;
                uint32_t dst = sbp + ((s + 1) & 1) * 32768;
                for (int idx = t; idx < cnt; idx += 256)
                    cp16(dst + idx * 16, src + (size_t)idx * 16);
                CP_COMMIT();
                CP_WAIT(1);
            } else {
                CP_WAIT(0);
            }
            __syncthreads();                      // buf s&1 data visible to all

            int r0 = s * 64;
            int cnt = min(64, n - r0);
            uint32_t buf = sbp + (s & 1) * 32768 + cl * 16;
            for (int i = rg; i < cnt; i += 8) {
                float w = wbuf[r0 + i];
                uint32_t q0, q1, q2, q3;
                asm volatile("ld.shared.v4.u32 {%0,%1,%2,%3}, [%4];"
                             : "=r"(q0), "=r"(q1), "=r"(q2), "=r"(q3)
                             : "r"(buf + (uint32_t)i * 512));
                float2 p;
                p = __half22float2(*(__half2*)&q0);
                ac[0] = fmaf(p.x, w, ac[0]); ac[1] = fmaf(p.y, w, ac[1]);
                p = __half22float2(*(__half2*)&q1);
                ac[2] = fmaf(p.x, w, ac[2]); ac[3] = fmaf(p.y, w, ac[3]);
                p = __half22float2(*(__half2*)&q2);
                ac[4] = fmaf(p.x, w, ac[4]); ac[5] = fmaf(p.y, w, ac[5]);
                p = __half22float2(*(__half2*)&q3);
                ac[6] = fmaf(p.x, w, ac[6]); ac[7] = fmaf(p.y, w, ac[7]);
            }
        }
        __syncthreads();                          // batch done before wbuf reuse
    }

    // reduce denominator
    red[t] = den; __syncthreads();
    #pragma unroll
    for (int st = 128; st > 0; st >>= 1) {
        if (t < st) red[t] += red[t + st];
        __syncthreads();
    }
    den = red[0] + 1e-9f;
    __syncthreads();

    // combine row-group partials
    #pragma unroll
    for (int h = 0; h < 8; h++) accs[rg * 256 + cl * 8 + h] = ac[h];
    __syncthreads();
    float s = 0.f;
    #pragma unroll
    for (int r = 0; r < 8; r++) s += accs[r * 256 + t];
    out[g * 256 + t] = s / den;
}

// ---------------- launch ----------------------------------------------------
extern "C" void kernel_launch(void* const* d_in, const int* in_sizes, int n_in,
                              void* d_out, int out_size) {
    const float* x = 0; const float* W1 = 0; const float* b1 = 0;
    const float* W2 = 0; const float* b2 = 0; const void* batch = 0;
    for (int i = 0; i < n_in; i++) {
        switch (in_sizes[i]) {
            case 67108864: x = (const float*)d_in[i]; break;
            case 65536:    W1 = (const float*)d_in[i]; break;
            case 262144:   batch = d_in[i]; break;
            case 1:        b2 = (const float*)d_in[i]; break;
            case 256:
                if (!b1) b1 = (const float*)d_in[i];
                else     W2 = (const float*)d_in[i];
                break;
            default: break;
        }
    }
    if (!x)     x     = (const float*)d_in[0];
    if (!W1)    W1    = (const float*)d_in[1];
    if (!b1)    b1    = (const float*)d_in[2];
    if (!W2)    W2    = (const float*)d_in[3];
    if (!b2)    b2    = (const float*)d_in[4];
    if (!batch) batch = d_in[5];

    cudaFuncSetAttribute(k_scores, cudaFuncAttributeMaxDynamicSharedMemorySize,
                         SMEM_SCORES_TOTAL);
    cudaFuncSetAttribute(k_pool, cudaFuncAttributeMaxDynamicSharedMemorySize,
                         SMEM_POOL_TOTAL);

    k_prep<<<260, 256>>>(W1, batch);
    k_scores<<<NROWS / 128, 256, SMEM_SCORES_TOTAL>>>(x, b1, W2, b2);
    k_pool<<<NSEG, 256, SMEM_POOL_TOTAL>>>((float*)d_out);
}